// round 2
// baseline (speedup 1.0000x reference)
#include <cuda_runtime.h>
#include <cuda_bf16.h>
#include <cstddef>

// ---------------- problem constants ----------------
#define EPSB 1e-5f
constexpr int Bk   = 16;
constexpr int Pk   = 2048;
constexpr int KN   = 5;
constexpr int NPTS = Bk * Pk;       // 32768
constexpr int NEDG = NPTS * KN;     // 163840
constexpr int NBLK = 256;           // stat partial blocks

// ---------------- scratch (device globals; no runtime allocation) ----------
__device__ float g_Z1[(size_t)NEDG * 64];     // z1, reused for z3
__device__ float g_Z2[(size_t)NEDG * 64];
__device__ float g_Z4[(size_t)NEDG * 128];
__device__ float g_H [(size_t)NPTS * 1024];
__device__ float g_X12[(size_t)NPTS * 192];   // cols 0..63 = x1, 64..191 = x2
__device__ float g_sq[NPTS];
__device__ int   g_idx1[NEDG];
__device__ int   g_idx2[NEDG];
__device__ float g_part[(size_t)NBLK * 2 * 1024];
__device__ float g_s1[64],  g_h1[64];
__device__ float g_s2[64],  g_h2[64];
__device__ float g_s3[64],  g_h3[64];
__device__ float g_s4[128], g_h4[128];
__device__ float g_s5[1024],g_h5[1024];
__device__ float g_s6[512], g_h6[512];
__device__ float g_s7[256], g_h7[256];
__device__ float g_eb2[64], g_eb3[64], g_ebm2[256], g_ebm3[2];
__device__ float g_P1[16 * 1024];
__device__ float g_Zm1[16 * 512];
__device__ float g_Zm2[16 * 256];

// ---------------- helpers ----------------
__device__ __forceinline__ void knn_insert(float d, int j, float bd[KN], int bi[KN]) {
#pragma unroll
    for (int k = 0; k < KN; k++) {
        if (d < bd[k]) {
            float td = bd[k]; int ti = bi[k];
            bd[k] = d; bi[k] = j;
            d = td; j = ti;
        }
    }
}

// ---------------- kNN on positions (D=3) ----------------
__global__ void knn3_k(const float* __restrict__ pos, int* __restrict__ idx) {
    __shared__ float sx[Pk], sy[Pk], sz[Pk], sn[Pk];
    int b  = blockIdx.x >> 3;            // 8 blocks per batch
    int p0 = (blockIdx.x & 7) << 8;
    const float* base = pos + (size_t)b * Pk * 3;
    for (int j = threadIdx.x; j < Pk; j += 256) {
        float x = base[3 * j], y = base[3 * j + 1], z = base[3 * j + 2];
        sx[j] = x; sy[j] = y; sz[j] = z;
        sn[j] = x * x + y * y + z * z;
    }
    __syncthreads();
    int p = p0 + threadIdx.x;
    float x = sx[p], y = sy[p], z = sz[p], sq = sn[p];
    float bd[KN]; int bi[KN];
#pragma unroll
    for (int k = 0; k < KN; k++) { bd[k] = 1e30f; bi[k] = 0; }
    for (int j = 0; j < Pk; j++) {
        float dot = x * sx[j] + y * sy[j] + z * sz[j];
        float d = sq + sn[j] - 2.f * dot;
        if (d < bd[KN - 1]) knn_insert(d, j, bd, bi);
    }
    int o = (b * Pk + p) * KN;
#pragma unroll
    for (int k = 0; k < KN; k++) idx[o + k] = bi[k];
}

// ---------------- EdgeConv1 layer0: edges(6) -> 64, ReLU ----------------
__global__ void ec1_l0_k(const float* __restrict__ pos, const int* __restrict__ idx,
                         const float* __restrict__ w, const float* __restrict__ bias,
                         float* __restrict__ Z) {
    __shared__ float sw[6 * 64];
    __shared__ float sb[64];
    if (threadIdx.x < 64) sb[threadIdx.x] = bias[threadIdx.x];
    for (int i = threadIdx.x; i < 384; i += 256) sw[i] = w[i];
    __syncthreads();
    int g = blockIdx.x * 256 + threadIdx.x;   // g = edge*4 + quarter
    int e = g >> 2, q = g & 3;
    int pt = e / KN;
    int b  = pt >> 11;
    int j  = idx[e];
    const float* pi = pos + (size_t)pt * 3;
    const float* pj = pos + ((size_t)(b << 11) + j) * 3;
    float e0 = pi[0], e1 = pi[1], e2 = pi[2];
    float e3 = pj[0] - e0, e4 = pj[1] - e1, e5 = pj[2] - e2;
    int c0 = q * 16;
    float out[16];
#pragma unroll
    for (int c = 0; c < 16; c++) {
        int cc = c0 + c;
        float a = sb[cc];
        a = fmaf(e0, sw[0 * 64 + cc], a);
        a = fmaf(e1, sw[1 * 64 + cc], a);
        a = fmaf(e2, sw[2 * 64 + cc], a);
        a = fmaf(e3, sw[3 * 64 + cc], a);
        a = fmaf(e4, sw[4 * 64 + cc], a);
        a = fmaf(e5, sw[5 * 64 + cc], a);
        out[c] = fmaxf(a, 0.f);
    }
    float4* dst = reinterpret_cast<float4*>(Z + (size_t)e * 64 + c0);
#pragma unroll
    for (int v = 0; v < 4; v++)
        dst[v] = make_float4(out[v * 4], out[v * 4 + 1], out[v * 4 + 2], out[v * 4 + 3]);
}

// ---------------- per-channel stats partials (deterministic) ----------------
template <int C>
__global__ void stats_k(const float* __restrict__ Z, int rpb) {
    __shared__ float ssum[256], ssq[256];
    int row0 = blockIdx.x * rpb;
    if (C >= 256) {
#pragma unroll
        for (int m = 0; m < C / 256; m++) {
            int c = threadIdx.x + m * 256;
            float s = 0.f, q = 0.f;
            for (int r = 0; r < rpb; r++) {
                float v = Z[(size_t)(row0 + r) * C + c];
                s += v; q += v * v;
            }
            g_part[((size_t)blockIdx.x * 2 + 0) * C + c] = s;
            g_part[((size_t)blockIdx.x * 2 + 1) * C + c] = q;
        }
    } else {
        const int ns = 256 / C;
        int c  = threadIdx.x % C;
        int sl = threadIdx.x / C;
        int rs = rpb / ns;
        float s = 0.f, q = 0.f;
        for (int r = sl * rs; r < (sl + 1) * rs; r++) {
            float v = Z[(size_t)(row0 + r) * C + c];
            s += v; q += v * v;
        }
        ssum[threadIdx.x] = s; ssq[threadIdx.x] = q;
        __syncthreads();
        if (sl == 0) {
            for (int m = 1; m < ns; m++) { s += ssum[m * C + c]; q += ssq[m * C + c]; }
            g_part[((size_t)blockIdx.x * 2 + 0) * C + c] = s;
            g_part[((size_t)blockIdx.x * 2 + 1) * C + c] = q;
        }
    }
}

__global__ void finalize_k(int C, float n, const float* __restrict__ g,
                           const float* __restrict__ be,
                           float* __restrict__ scale, float* __restrict__ shift) {
    int c = blockIdx.x * blockDim.x + threadIdx.x;
    if (c >= C) return;
    double s = 0.0, q = 0.0;
    for (int b = 0; b < NBLK; b++) {
        s += (double)g_part[((size_t)b * 2 + 0) * C + c];
        q += (double)g_part[((size_t)b * 2 + 1) * C + c];
    }
    float mean = (float)(s / (double)n);
    float var  = (float)(q / (double)n) - mean * mean;
    float sc = g[c] * rsqrtf(var + EPSB);
    scale[c] = sc;
    shift[c] = be[c] - mean * sc;
}

__global__ void foldbias_k(int Cin, int Cout, const float* __restrict__ w,
                           const float* __restrict__ bias, const float* __restrict__ shift,
                           float* __restrict__ eb) {
    int c = blockIdx.x * blockDim.x + threadIdx.x;
    if (c >= Cout) return;
    float a = bias[c];
    for (int r = 0; r < Cin; r++) a = fmaf(shift[r], w[(size_t)r * Cout + c], a);
    eb[c] = a;
}

// ---------------- 64->64 GEMM (BN-folded input), ReLU ----------------
__global__ void __launch_bounds__(256) ec_mid_k(const float* __restrict__ Zin,
                                                const float* __restrict__ w,
                                                const float* __restrict__ scaleIn,
                                                const float* __restrict__ eb,
                                                float* __restrict__ Zout) {
    __shared__ float At[64 * 68];  // At[k][r]
    __shared__ float Bs[64 * 68];  // Bs[k][c] (scaled)
    int row0 = blockIdx.x * 64;
    for (int i = threadIdx.x; i < 64 * 64; i += 256) {
        int r = i >> 6, k = i & 63;
        At[k * 68 + r] = Zin[(size_t)(row0 + r) * 64 + k];
    }
    for (int i = threadIdx.x; i < 64 * 64; i += 256) {
        int k = i >> 6, c = i & 63;
        Bs[k * 68 + c] = scaleIn[k] * w[i];
    }
    __syncthreads();
    int r0 = (threadIdx.x >> 4) * 4;
    int c0 = (threadIdx.x & 15) * 4;
    float acc[4][4] = {};
#pragma unroll 4
    for (int k = 0; k < 64; k++) {
        float4 a  = *reinterpret_cast<const float4*>(&At[k * 68 + r0]);
        float4 bv = *reinterpret_cast<const float4*>(&Bs[k * 68 + c0]);
        float aa[4] = {a.x, a.y, a.z, a.w};
        float bb[4] = {bv.x, bv.y, bv.z, bv.w};
#pragma unroll
        for (int ii = 0; ii < 4; ii++)
#pragma unroll
            for (int jj = 0; jj < 4; jj++)
                acc[ii][jj] = fmaf(aa[ii], bb[jj], acc[ii][jj]);
    }
    float e0 = eb[c0], e1 = eb[c0 + 1], e2 = eb[c0 + 2], e3 = eb[c0 + 3];
#pragma unroll
    for (int ii = 0; ii < 4; ii++) {
        float4 o;
        o.x = fmaxf(acc[ii][0] + e0, 0.f);
        o.y = fmaxf(acc[ii][1] + e1, 0.f);
        o.z = fmaxf(acc[ii][2] + e2, 0.f);
        o.w = fmaxf(acc[ii][3] + e3, 0.f);
        *reinterpret_cast<float4*>(&Zout[(size_t)(row0 + r0 + ii) * 64 + c0]) = o;
    }
}

// ---------------- k-max over edges + BN affine ----------------
__global__ void maxE_k(const float* __restrict__ Z, int C,
                       const float* __restrict__ scale, const float* __restrict__ shift,
                       float* __restrict__ X, int colOff) {
    int g = blockIdx.x * 256 + threadIdx.x;
    int per = C >> 2;
    int pt = g / per;
    int c4 = (g % per) * 4;
    float4 m = make_float4(-1e30f, -1e30f, -1e30f, -1e30f);
#pragma unroll
    for (int k = 0; k < KN; k++) {
        float4 v = *reinterpret_cast<const float4*>(&Z[(size_t)(pt * KN + k) * C + c4]);
        m.x = fmaxf(m.x, v.x); m.y = fmaxf(m.y, v.y);
        m.z = fmaxf(m.z, v.z); m.w = fmaxf(m.w, v.w);
    }
    float4 o;
    o.x = fmaf(scale[c4 + 0], m.x, shift[c4 + 0]);
    o.y = fmaf(scale[c4 + 1], m.y, shift[c4 + 1]);
    o.z = fmaf(scale[c4 + 2], m.z, shift[c4 + 2]);
    o.w = fmaf(scale[c4 + 3], m.w, shift[c4 + 3]);
    *reinterpret_cast<float4*>(&X[(size_t)pt * 192 + colOff + c4]) = o;
}

// ---------------- sq norms of x1 ----------------
__global__ void sqnorm_k() {
    int pt = blockIdx.x * 256 + threadIdx.x;
    const float4* x = reinterpret_cast<const float4*>(&g_X12[(size_t)pt * 192]);
    float s = 0.f;
#pragma unroll
    for (int i = 0; i < 16; i++) {
        float4 v = x[i];
        s += v.x * v.x + v.y * v.y + v.z * v.z + v.w * v.w;
    }
    g_sq[pt] = s;
}

// ---------------- kNN on 64-dim x1 ----------------
__global__ void __launch_bounds__(256) knn64_k(int* __restrict__ idx) {
    __shared__ float4 sq4[128 * 16];
    __shared__ float  ssn[128];
    int b = blockIdx.x >> 3;
    int p = ((blockIdx.x & 7) << 8) + threadIdx.x;
    int pt = (b << 11) + p;
    float4 xp[16];
#pragma unroll
    for (int i = 0; i < 16; i++)
        xp[i] = *reinterpret_cast<const float4*>(&g_X12[(size_t)pt * 192 + i * 4]);
    float sqp = g_sq[pt];
    float bd[KN]; int bi[KN];
#pragma unroll
    for (int k = 0; k < KN; k++) { bd[k] = 1e30f; bi[k] = 0; }
    for (int q0 = 0; q0 < Pk; q0 += 128) {
        __syncthreads();
        for (int t = threadIdx.x; t < 128 * 16; t += 256) {
            int qr = t >> 4, d4 = t & 15;
            sq4[qr * 16 + d4] = *reinterpret_cast<const float4*>(
                &g_X12[(size_t)((b << 11) + q0 + qr) * 192 + d4 * 4]);
        }
        if (threadIdx.x < 128) ssn[threadIdx.x] = g_sq[(b << 11) + q0 + threadIdx.x];
        __syncthreads();
        for (int qr = 0; qr < 128; qr++) {
            float dot = 0.f;
#pragma unroll
            for (int i = 0; i < 16; i++) {
                float4 qv = sq4[qr * 16 + i];
                dot = fmaf(xp[i].x, qv.x, dot);
                dot = fmaf(xp[i].y, qv.y, dot);
                dot = fmaf(xp[i].z, qv.z, dot);
                dot = fmaf(xp[i].w, qv.w, dot);
            }
            float d = sqp + ssn[qr] - 2.f * dot;
            if (d < bd[KN - 1]) knn_insert(d, q0 + qr, bd, bi);
        }
    }
    int o = pt * KN;
#pragma unroll
    for (int k = 0; k < KN; k++) idx[o + k] = bi[k];
}

// ---------------- EdgeConv2: gather(128) + GEMM 128->128, ReLU ----------------
__global__ void __launch_bounds__(256) ec2_k(const float* __restrict__ X,
                                             const int* __restrict__ idx,
                                             const float* __restrict__ w,
                                             const float* __restrict__ bias,
                                             float* __restrict__ Z) {
    __shared__ float At[128 * 68];  // e-features transposed [col][row]  (34.8KB)
    __shared__ float Bs[16 * 132];  // weight chunk [k][c]               (8.4KB)
    int e0 = blockIdx.x * 64;
    for (int i = threadIdx.x; i < 64 * 128; i += 256) {
        int r = i >> 7, col = i & 127;
        int e = e0 + r;
        int pt = e / KN;
        int bb = pt >> 11;
        int j  = idx[e];
        const float* xi = X + (size_t)pt * 192;
        const float* xj = X + ((size_t)(bb << 11) + j) * 192;
        float v = (col < 64) ? xi[col] : (xj[col - 64] - xi[col - 64]);
        At[col * 68 + r] = v;
    }
    int r0 = (threadIdx.x >> 4) * 4;
    int c0 = (threadIdx.x & 15) * 8;
    float acc[4][8] = {};
    for (int kc = 0; kc < 8; kc++) {
        __syncthreads();
        for (int i = threadIdx.x; i < 16 * 128; i += 256) {
            int kk = i >> 7, c = i & 127;
            Bs[kk * 132 + c] = w[(size_t)(kc * 16 + kk) * 128 + c];
        }
        __syncthreads();
#pragma unroll
        for (int kk = 0; kk < 16; kk++) {
            float4 a  = *reinterpret_cast<const float4*>(&At[(kc * 16 + kk) * 68 + r0]);
            float4 b0 = *reinterpret_cast<const float4*>(&Bs[kk * 132 + c0]);
            float4 b1 = *reinterpret_cast<const float4*>(&Bs[kk * 132 + c0 + 4]);
            float aa[4] = {a.x, a.y, a.z, a.w};
            float bb8[8] = {b0.x, b0.y, b0.z, b0.w, b1.x, b1.y, b1.z, b1.w};
#pragma unroll
            for (int ii = 0; ii < 4; ii++)
#pragma unroll
                for (int jj = 0; jj < 8; jj++)
                    acc[ii][jj] = fmaf(aa[ii], bb8[jj], acc[ii][jj]);
        }
    }
    float bv[8];
#pragma unroll
    for (int jj = 0; jj < 8; jj++) bv[jj] = bias[c0 + jj];
#pragma unroll
    for (int ii = 0; ii < 4; ii++) {
        float4 o0, o1;
        o0.x = fmaxf(acc[ii][0] + bv[0], 0.f);
        o0.y = fmaxf(acc[ii][1] + bv[1], 0.f);
        o0.z = fmaxf(acc[ii][2] + bv[2], 0.f);
        o0.w = fmaxf(acc[ii][3] + bv[3], 0.f);
        o1.x = fmaxf(acc[ii][4] + bv[4], 0.f);
        o1.y = fmaxf(acc[ii][5] + bv[5], 0.f);
        o1.z = fmaxf(acc[ii][6] + bv[6], 0.f);
        o1.w = fmaxf(acc[ii][7] + bv[7], 0.f);
        size_t off = (size_t)(e0 + r0 + ii) * 128 + c0;
        *reinterpret_cast<float4*>(&Z[off])     = o0;
        *reinterpret_cast<float4*>(&Z[off + 4]) = o1;
    }
}

// ---------------- l1: [NPTS,192] @ [192,1024] + bias, ReLU ----------------
__global__ void __launch_bounds__(256) l1_k(const float* __restrict__ X,
                                            const float* __restrict__ w,
                                            const float* __restrict__ bias,
                                            float* __restrict__ H) {
    __shared__ float At[32 * 68];
    __shared__ float Bs[32 * 132];
    int row0 = (blockIdx.x >> 3) * 64;
    int col0 = (blockIdx.x & 7) * 128;
    int r0 = (threadIdx.x >> 4) * 4;
    int c0 = (threadIdx.x & 15) * 8;
    float acc[4][8] = {};
    for (int kc = 0; kc < 6; kc++) {
        __syncthreads();
        for (int i = threadIdx.x; i < 64 * 32; i += 256) {
            int r = i >> 5, k = i & 31;
            At[k * 68 + r] = X[(size_t)(row0 + r) * 192 + kc * 32 + k];
        }
        for (int i = threadIdx.x; i < 32 * 128; i += 256) {
            int kk = i >> 7, c = i & 127;
            Bs[kk * 132 + c] = w[(size_t)(kc * 32 + kk) * 1024 + col0 + c];
        }
        __syncthreads();
#pragma unroll
        for (int kk = 0; kk < 32; kk++) {
            float4 a  = *reinterpret_cast<const float4*>(&At[kk * 68 + r0]);
            float4 b0 = *reinterpret_cast<const float4*>(&Bs[kk * 132 + c0]);
            float4 b1 = *reinterpret_cast<const float4*>(&Bs[kk * 132 + c0 + 4]);
            float aa[4] = {a.x, a.y, a.z, a.w};
            float bb8[8] = {b0.x, b0.y, b0.z, b0.w, b1.x, b1.y, b1.z, b1.w};
#pragma unroll
            for (int ii = 0; ii < 4; ii++)
#pragma unroll
                for (int jj = 0; jj < 8; jj++)
                    acc[ii][jj] = fmaf(aa[ii], bb8[jj], acc[ii][jj]);
        }
    }
    float bv[8];
#pragma unroll
    for (int jj = 0; jj < 8; jj++) bv[jj] = bias[col0 + c0 + jj];
#pragma unroll
    for (int ii = 0; ii < 4; ii++) {
        float4 o0, o1;
        o0.x = fmaxf(acc[ii][0] + bv[0], 0.f);
        o0.y = fmaxf(acc[ii][1] + bv[1], 0.f);
        o0.z = fmaxf(acc[ii][2] + bv[2], 0.f);
        o0.w = fmaxf(acc[ii][3] + bv[3], 0.f);
        o1.x = fmaxf(acc[ii][4] + bv[4], 0.f);
        o1.y = fmaxf(acc[ii][5] + bv[5], 0.f);
        o1.z = fmaxf(acc[ii][6] + bv[6], 0.f);
        o1.w = fmaxf(acc[ii][7] + bv[7], 0.f);
        size_t off = (size_t)(row0 + r0 + ii) * 1024 + col0 + c0;
        *reinterpret_cast<float4*>(&H[off])     = o0;
        *reinterpret_cast<float4*>(&H[off + 4]) = o1;
    }
}

// ---------------- global max pool + BN affine ----------------
__global__ void pool_k() {
    int g = blockIdx.x * 256 + threadIdx.x;  // 16*1024
    int b = g >> 10, c = g & 1023;
    float m = -1e30f;
    size_t base = (size_t)(b << 11) * 1024 + c;
    for (int p = 0; p < Pk; p++) m = fmaxf(m, g_H[base + (size_t)p * 1024]);
    g_P1[g] = fmaf(g_s5[c], m, g_h5[c]);
}

// ---------------- head ----------------
__global__ void head1_k(const float* __restrict__ w, const float* __restrict__ bias) {
    int g = blockIdx.x * 256 + threadIdx.x;  // 16*512
    int b = g >> 9, c = g & 511;
    float a = bias[c];
    const float* p = g_P1 + (b << 10);
    for (int r = 0; r < 1024; r++) a = fmaf(p[r], w[(size_t)r * 512 + c], a);
    g_Zm1[g] = fmaxf(a, 0.f);
}

__global__ void stats16_k(const float* __restrict__ Z, int C,
                          const float* __restrict__ g, const float* __restrict__ be,
                          float* __restrict__ scale, float* __restrict__ shift) {
    int c = blockIdx.x * blockDim.x + threadIdx.x;
    if (c >= C) return;
    float s = 0.f, q = 0.f;
    for (int b = 0; b < 16; b++) { float v = Z[b * C + c]; s += v; q += v * v; }
    float mean = s * (1.f / 16.f);
    float var  = q * (1.f / 16.f) - mean * mean;
    float sc = g[c] * rsqrtf(var + EPSB);
    scale[c] = sc;
    shift[c] = be[c] - mean * sc;
}

__global__ void head2_k(const float* __restrict__ w) {
    int g = blockIdx.x * 256 + threadIdx.x;  // 16*256
    int b = g >> 8, c = g & 255;
    float a = g_ebm2[c];
    const float* z = g_Zm1 + b * 512;
    for (int r = 0; r < 512; r++) a = fmaf(z[r] * g_s6[r], w[(size_t)r * 256 + c], a);
    g_Zm2[g] = fmaxf(a, 0.f);
}

__global__ void head3_k(const float* __restrict__ w, float* __restrict__ out) {
    int t = threadIdx.x;
    if (t >= 32) return;
    int b = t >> 1, n = t & 1;
    float a = g_ebm3[n];
    const float* z = g_Zm2 + b * 256;
    for (int r = 0; r < 256; r++) a = fmaf(z[r] * g_s7[r], w[r * 2 + n], a);
    out[b * 2 + n] = a;
}

// ---------------- launch ----------------
extern "C" void kernel_launch(void* const* d_in, const int* in_sizes, int n_in,
                              void* d_out, int out_size) {
    const float* pos  = (const float*)d_in[0];
    const float* c1w0 = (const float*)d_in[1];
    const float* c1b0 = (const float*)d_in[2];
    const float* c1g0 = (const float*)d_in[3];
    const float* c1e0 = (const float*)d_in[4];
    const float* c1w1 = (const float*)d_in[5];
    const float* c1b1 = (const float*)d_in[6];
    const float* c1g1 = (const float*)d_in[7];
    const float* c1e1 = (const float*)d_in[8];
    const float* c1w2 = (const float*)d_in[9];
    const float* c1b2 = (const float*)d_in[10];
    const float* c1g2 = (const float*)d_in[11];
    const float* c1e2 = (const float*)d_in[12];
    const float* c2w  = (const float*)d_in[13];
    const float* c2b  = (const float*)d_in[14];
    const float* c2g  = (const float*)d_in[15];
    const float* c2e  = (const float*)d_in[16];
    const float* l1w  = (const float*)d_in[17];
    const float* l1b  = (const float*)d_in[18];
    const float* l1g  = (const float*)d_in[19];
    const float* l1e  = (const float*)d_in[20];
    const float* m1w  = (const float*)d_in[21];
    const float* m1b  = (const float*)d_in[22];
    const float* m1g  = (const float*)d_in[23];
    const float* m1e  = (const float*)d_in[24];
    const float* m2w  = (const float*)d_in[25];
    const float* m2b  = (const float*)d_in[26];
    const float* m2g  = (const float*)d_in[27];
    const float* m2e  = (const float*)d_in[28];
    const float* m3w  = (const float*)d_in[29];
    const float* m3b  = (const float*)d_in[30];

    void *pZ1, *pZ2, *pZ4, *pH, *pX, *pI1, *pI2;
    void *ps1, *ph1, *ps2, *ph2, *ps3, *ph3, *ps4, *ph4, *ps5, *ph5, *ps6, *ph6, *ps7, *ph7;
    void *peb2, *peb3, *pebm2, *pebm3, *pZm1, *pZm2;
    cudaGetSymbolAddress(&pZ1, g_Z1);
    cudaGetSymbolAddress(&pZ2, g_Z2);
    cudaGetSymbolAddress(&pZ4, g_Z4);
    cudaGetSymbolAddress(&pH,  g_H);
    cudaGetSymbolAddress(&pX,  g_X12);
    cudaGetSymbolAddress(&pI1, g_idx1);
    cudaGetSymbolAddress(&pI2, g_idx2);
    cudaGetSymbolAddress(&ps1, g_s1); cudaGetSymbolAddress(&ph1, g_h1);
    cudaGetSymbolAddress(&ps2, g_s2); cudaGetSymbolAddress(&ph2, g_h2);
    cudaGetSymbolAddress(&ps3, g_s3); cudaGetSymbolAddress(&ph3, g_h3);
    cudaGetSymbolAddress(&ps4, g_s4); cudaGetSymbolAddress(&ph4, g_h4);
    cudaGetSymbolAddress(&ps5, g_s5); cudaGetSymbolAddress(&ph5, g_h5);
    cudaGetSymbolAddress(&ps6, g_s6); cudaGetSymbolAddress(&ph6, g_h6);
    cudaGetSymbolAddress(&ps7, g_s7); cudaGetSymbolAddress(&ph7, g_h7);
    cudaGetSymbolAddress(&peb2, g_eb2); cudaGetSymbolAddress(&peb3, g_eb3);
    cudaGetSymbolAddress(&pebm2, g_ebm2); cudaGetSymbolAddress(&pebm3, g_ebm3);
    cudaGetSymbolAddress(&pZm1, g_Zm1); cudaGetSymbolAddress(&pZm2, g_Zm2);

    float* Z1 = (float*)pZ1;  float* Z2 = (float*)pZ2;  float* Z4 = (float*)pZ4;
    float* H  = (float*)pH;   float* X  = (float*)pX;
    int* I1 = (int*)pI1;      int* I2 = (int*)pI2;

    // --- EdgeConv1 ---
    knn3_k<<<128, 256>>>(pos, I1);
    ec1_l0_k<<<NEDG * 4 / 256, 256>>>(pos, I1, c1w0, c1b0, Z1);
    stats_k<64><<<NBLK, 256>>>(Z1, NEDG / NBLK);
    finalize_k<<<1, 64>>>(64, (float)NEDG, c1g0, c1e0, (float*)ps1, (float*)ph1);
    foldbias_k<<<1, 64>>>(64, 64, c1w1, c1b1, (float*)ph1, (float*)peb2);
    ec_mid_k<<<NEDG / 64, 256>>>(Z1, c1w1, (float*)ps1, (float*)peb2, Z2);
    stats_k<64><<<NBLK, 256>>>(Z2, NEDG / NBLK);
    finalize_k<<<1, 64>>>(64, (float)NEDG, c1g1, c1e1, (float*)ps2, (float*)ph2);
    foldbias_k<<<1, 64>>>(64, 64, c1w2, c1b2, (float*)ph2, (float*)peb3);
    ec_mid_k<<<NEDG / 64, 256>>>(Z2, c1w2, (float*)ps2, (float*)peb3, Z1);
    stats_k<64><<<NBLK, 256>>>(Z1, NEDG / NBLK);
    finalize_k<<<1, 64>>>(64, (float)NEDG, c1g2, c1e2, (float*)ps3, (float*)ph3);
    maxE_k<<<NPTS * 16 / 256, 256>>>(Z1, 64, (float*)ps3, (float*)ph3, X, 0);

    // --- EdgeConv2 ---
    sqnorm_k<<<NPTS / 256, 256>>>();
    knn64_k<<<128, 256>>>(I2);
    ec2_k<<<NEDG / 64, 256>>>(X, I2, c2w, c2b, Z4);
    stats_k<128><<<NBLK, 256>>>(Z4, NEDG / NBLK);
    finalize_k<<<1, 128>>>(128, (float)NEDG, c2g, c2e, (float*)ps4, (float*)ph4);
    maxE_k<<<NPTS * 32 / 256, 256>>>(Z4, 128, (float*)ps4, (float*)ph4, X, 64);

    // --- l1 + pool ---
    l1_k<<<(NPTS / 64) * 8, 256>>>(X, l1w, l1b, H);
    stats_k<1024><<<NBLK, 256>>>(H, NPTS / NBLK);
    finalize_k<<<4, 256>>>(1024, (float)NPTS, l1g, l1e, (float*)ps5, (float*)ph5);
    pool_k<<<64, 256>>>();

    // --- head ---
    head1_k<<<32, 256>>>(m1w, m1b);
    stats16_k<<<2, 256>>>((float*)pZm1, 512, m1g, m1e, (float*)ps6, (float*)ph6);
    foldbias_k<<<1, 256>>>(512, 256, m2w, m2b, (float*)ph6, (float*)pebm2);
    head2_k<<<16, 256>>>(m2w);
    stats16_k<<<1, 256>>>((float*)pZm2, 256, m2g, m2e, (float*)ps7, (float*)ph7);
    foldbias_k<<<1, 32>>>(256, 2, m3w, m3b, (float*)ph7, (float*)pebm3);
    head3_k<<<1, 32>>>(m3w, (float*)d_out);
}

// round 3
// speedup vs baseline: 1.3094x; 1.3094x over previous
#include <cuda_runtime.h>
#include <cuda_bf16.h>
#include <cstddef>

// ---------------- problem constants ----------------
#define EPSB 1e-5f
constexpr int Bk   = 16;
constexpr int Pk   = 2048;
constexpr int KN   = 5;
constexpr int NPTS = Bk * Pk;       // 32768
constexpr int NEDG = NPTS * KN;     // 163840
constexpr int NBLK = 256;           // stat partial blocks (edge tensors)
constexpr int HRB  = NPTS / 64;     // 512 row-blocks for fused l1 stats

using u64 = unsigned long long;

// ---------------- scratch (device globals; no runtime allocation) ----------
__device__ float g_Z1[(size_t)NEDG * 64];
__device__ float g_Z2[(size_t)NEDG * 64];
__device__ float g_Z4[(size_t)NEDG * 128];
__device__ float g_X12[(size_t)NPTS * 192];   // cols 0..63 = x1, 64..191 = x2
__device__ float g_sq[NPTS];
__device__ int   g_idx1[NEDG];
__device__ int   g_idx2[NEDG];
__device__ float g_part[(size_t)HRB * 2 * 1024];   // 4MB partial sums/sumsq
__device__ float g_s1[64],  g_h1[64];
__device__ float g_s2[64],  g_h2[64];
__device__ float g_s3[64],  g_h3[64];
__device__ float g_s4[128], g_h4[128];
__device__ float g_s5[1024],g_h5[1024];
__device__ float g_s6[512], g_h6[512];
__device__ float g_s7[256], g_h7[256];
__device__ float g_eb2[64], g_eb3[64], g_ebm2[256], g_ebm3[2];
__device__ int   g_P1raw[16 * 1024];
__device__ float g_P1[16 * 1024];
__device__ float g_Zm1[16 * 512];
__device__ float g_Zm2[16 * 256];

// ---------------- f32x2 packed-FMA helpers ----------------
__device__ __forceinline__ u64 pack2(float lo, float hi) {
    u64 r; asm("mov.b64 %0, {%1, %2};" : "=l"(r) : "f"(lo), "f"(hi)); return r;
}
__device__ __forceinline__ float2 unpack2(u64 v) {
    float2 r; asm("mov.b64 {%0, %1}, %2;" : "=f"(r.x), "=f"(r.y) : "l"(v)); return r;
}
__device__ __forceinline__ void fma2(u64& d, u64 a, u64 b) {
    asm("fma.rn.f32x2 %0, %1, %2, %0;" : "+l"(d) : "l"(a), "l"(b));
}

// ---------------- helpers ----------------
__device__ __forceinline__ void knn_insert(float d, int j, float bd[KN], int bi[KN]) {
#pragma unroll
    for (int k = 0; k < KN; k++) {
        if (d < bd[k]) {
            float td = bd[k]; int ti = bi[k];
            bd[k] = d; bi[k] = j;
            d = td; j = ti;
        }
    }
}

// ---------------- kNN on positions (D=3) ----------------
__global__ void knn3_k(const float* __restrict__ pos, int* __restrict__ idx) {
    __shared__ float sx[Pk], sy[Pk], sz[Pk], sn[Pk];
    int b  = blockIdx.x >> 3;
    int p0 = (blockIdx.x & 7) << 8;
    const float* base = pos + (size_t)b * Pk * 3;
    for (int j = threadIdx.x; j < Pk; j += 256) {
        float x = base[3 * j], y = base[3 * j + 1], z = base[3 * j + 2];
        sx[j] = x; sy[j] = y; sz[j] = z;
        sn[j] = x * x + y * y + z * z;
    }
    __syncthreads();
    int p = p0 + threadIdx.x;
    float x = sx[p], y = sy[p], z = sz[p], sq = sn[p];
    float bd[KN]; int bi[KN];
#pragma unroll
    for (int k = 0; k < KN; k++) { bd[k] = 1e30f; bi[k] = 0; }
    for (int j = 0; j < Pk; j++) {
        float dot = x * sx[j] + y * sy[j] + z * sz[j];
        float d = sq + sn[j] - 2.f * dot;
        if (d < bd[KN - 1]) knn_insert(d, j, bd, bi);
    }
    int o = (b * Pk + p) * KN;
#pragma unroll
    for (int k = 0; k < KN; k++) idx[o + k] = bi[k];
}

// ---------------- EdgeConv1 layer0: edges(6) -> 64, ReLU ----------------
__global__ void ec1_l0_k(const float* __restrict__ pos, const int* __restrict__ idx,
                         const float* __restrict__ w, const float* __restrict__ bias,
                         float* __restrict__ Z) {
    __shared__ float sw[6 * 64];
    __shared__ float sb[64];
    if (threadIdx.x < 64) sb[threadIdx.x] = bias[threadIdx.x];
    for (int i = threadIdx.x; i < 384; i += 256) sw[i] = w[i];
    __syncthreads();
    int g = blockIdx.x * 256 + threadIdx.x;
    int e = g >> 2, q = g & 3;
    int pt = e / KN;
    int b  = pt >> 11;
    int j  = idx[e];
    const float* pi = pos + (size_t)pt * 3;
    const float* pj = pos + ((size_t)(b << 11) + j) * 3;
    float e0 = pi[0], e1 = pi[1], e2 = pi[2];
    float e3 = pj[0] - e0, e4 = pj[1] - e1, e5 = pj[2] - e2;
    int c0 = q * 16;
    float out[16];
#pragma unroll
    for (int c = 0; c < 16; c++) {
        int cc = c0 + c;
        float a = sb[cc];
        a = fmaf(e0, sw[0 * 64 + cc], a);
        a = fmaf(e1, sw[1 * 64 + cc], a);
        a = fmaf(e2, sw[2 * 64 + cc], a);
        a = fmaf(e3, sw[3 * 64 + cc], a);
        a = fmaf(e4, sw[4 * 64 + cc], a);
        a = fmaf(e5, sw[5 * 64 + cc], a);
        out[c] = fmaxf(a, 0.f);
    }
    float4* dst = reinterpret_cast<float4*>(Z + (size_t)e * 64 + c0);
#pragma unroll
    for (int v = 0; v < 4; v++)
        dst[v] = make_float4(out[v * 4], out[v * 4 + 1], out[v * 4 + 2], out[v * 4 + 3]);
}

// ---------------- per-channel stats partials (deterministic) ----------------
template <int C>
__global__ void stats_k(const float* __restrict__ Z, int rpb) {
    __shared__ float ssum[256], ssq[256];
    int row0 = blockIdx.x * rpb;
    if (C >= 256) {
#pragma unroll
        for (int m = 0; m < C / 256; m++) {
            int c = threadIdx.x + m * 256;
            float s = 0.f, q = 0.f;
            for (int r = 0; r < rpb; r++) {
                float v = Z[(size_t)(row0 + r) * C + c];
                s += v; q += v * v;
            }
            g_part[((size_t)blockIdx.x * 2 + 0) * C + c] = s;
            g_part[((size_t)blockIdx.x * 2 + 1) * C + c] = q;
        }
    } else {
        const int ns = 256 / C;
        int c  = threadIdx.x % C;
        int sl = threadIdx.x / C;
        int rs = rpb / ns;
        float s = 0.f, q = 0.f;
        for (int r = sl * rs; r < (sl + 1) * rs; r++) {
            float v = Z[(size_t)(row0 + r) * C + c];
            s += v; q += v * v;
        }
        ssum[threadIdx.x] = s; ssq[threadIdx.x] = q;
        __syncthreads();
        if (sl == 0) {
            for (int m = 1; m < ns; m++) { s += ssum[m * C + c]; q += ssq[m * C + c]; }
            g_part[((size_t)blockIdx.x * 2 + 0) * C + c] = s;
            g_part[((size_t)blockIdx.x * 2 + 1) * C + c] = q;
        }
    }
}

// one warp per channel, parallel over partial blocks
__global__ void finalize_k(int C, float n, int nblk, const float* __restrict__ g,
                           const float* __restrict__ be,
                           float* __restrict__ scale, float* __restrict__ shift) {
    int warp = (blockIdx.x * blockDim.x + threadIdx.x) >> 5;
    int lane = threadIdx.x & 31;
    if (warp >= C) return;
    float s = 0.f, q = 0.f;
    for (int b = lane; b < nblk; b += 32) {
        s += g_part[((size_t)b * 2 + 0) * C + warp];
        q += g_part[((size_t)b * 2 + 1) * C + warp];
    }
#pragma unroll
    for (int o = 16; o; o >>= 1) {
        s += __shfl_xor_sync(0xffffffffu, s, o);
        q += __shfl_xor_sync(0xffffffffu, q, o);
    }
    if (lane == 0) {
        float mean = s / n;
        float var  = q / n - mean * mean;
        float sc = g[warp] * rsqrtf(var + EPSB);
        scale[warp] = sc;
        shift[warp] = be[warp] - mean * sc;
    }
}

__global__ void foldbias_k(int Cin, int Cout, const float* __restrict__ w,
                           const float* __restrict__ bias, const float* __restrict__ shift,
                           float* __restrict__ eb) {
    int c = blockIdx.x * blockDim.x + threadIdx.x;
    if (c >= Cout) return;
    float a = bias[c];
    for (int r = 0; r < Cin; r++) a = fmaf(shift[r], w[(size_t)r * Cout + c], a);
    eb[c] = a;
}

// ---------------- 64->64 GEMM (BN-folded input), ReLU, f32x2 ----------------
__global__ void __launch_bounds__(256) ec_mid_k(const float* __restrict__ Zin,
                                                const float* __restrict__ w,
                                                const float* __restrict__ scaleIn,
                                                const float* __restrict__ eb,
                                                float* __restrict__ Zout) {
    __shared__ __align__(16) float At[64 * 68];
    __shared__ __align__(16) float Bs[64 * 68];
    int row0 = blockIdx.x * 64;
    for (int i = threadIdx.x; i < 64 * 64; i += 256) {
        int r = i >> 6, k = i & 63;
        At[k * 68 + r] = Zin[(size_t)(row0 + r) * 64 + k];
    }
    for (int i = threadIdx.x; i < 64 * 64; i += 256) {
        int k = i >> 6, c = i & 63;
        Bs[k * 68 + c] = scaleIn[k] * w[i];
    }
    __syncthreads();
    int r0 = (threadIdx.x >> 4) * 4;
    int c0 = (threadIdx.x & 15) * 4;
    u64 acc2[4][2] = {};
#pragma unroll 4
    for (int k = 0; k < 64; k++) {
        float4 a  = *reinterpret_cast<const float4*>(&At[k * 68 + r0]);
        u64 b0 = *reinterpret_cast<const u64*>(&Bs[k * 68 + c0]);
        u64 b1 = *reinterpret_cast<const u64*>(&Bs[k * 68 + c0 + 2]);
        float aa[4] = {a.x, a.y, a.z, a.w};
#pragma unroll
        for (int ii = 0; ii < 4; ii++) {
            u64 ad = pack2(aa[ii], aa[ii]);
            fma2(acc2[ii][0], ad, b0);
            fma2(acc2[ii][1], ad, b1);
        }
    }
    float e0 = eb[c0], e1 = eb[c0 + 1], e2 = eb[c0 + 2], e3 = eb[c0 + 3];
#pragma unroll
    for (int ii = 0; ii < 4; ii++) {
        float2 p0 = unpack2(acc2[ii][0]);
        float2 p1 = unpack2(acc2[ii][1]);
        float4 o;
        o.x = fmaxf(p0.x + e0, 0.f);
        o.y = fmaxf(p0.y + e1, 0.f);
        o.z = fmaxf(p1.x + e2, 0.f);
        o.w = fmaxf(p1.y + e3, 0.f);
        *reinterpret_cast<float4*>(&Zout[(size_t)(row0 + r0 + ii) * 64 + c0]) = o;
    }
}

// ---------------- k-max over edges + BN affine ----------------
__global__ void maxE_k(const float* __restrict__ Z, int C,
                       const float* __restrict__ scale, const float* __restrict__ shift,
                       float* __restrict__ X, int colOff) {
    int g = blockIdx.x * 256 + threadIdx.x;
    int per = C >> 2;
    int pt = g / per;
    int c4 = (g % per) * 4;
    float4 m = make_float4(-1e30f, -1e30f, -1e30f, -1e30f);
#pragma unroll
    for (int k = 0; k < KN; k++) {
        float4 v = *reinterpret_cast<const float4*>(&Z[(size_t)(pt * KN + k) * C + c4]);
        m.x = fmaxf(m.x, v.x); m.y = fmaxf(m.y, v.y);
        m.z = fmaxf(m.z, v.z); m.w = fmaxf(m.w, v.w);
    }
    float4 o;
    o.x = fmaf(scale[c4 + 0], m.x, shift[c4 + 0]);
    o.y = fmaf(scale[c4 + 1], m.y, shift[c4 + 1]);
    o.z = fmaf(scale[c4 + 2], m.z, shift[c4 + 2]);
    o.w = fmaf(scale[c4 + 3], m.w, shift[c4 + 3]);
    *reinterpret_cast<float4*>(&X[(size_t)pt * 192 + colOff + c4]) = o;
}

// ---------------- sq norms of x1 ----------------
__global__ void sqnorm_k() {
    int pt = blockIdx.x * 256 + threadIdx.x;
    const float4* x = reinterpret_cast<const float4*>(&g_X12[(size_t)pt * 192]);
    float s = 0.f;
#pragma unroll
    for (int i = 0; i < 16; i++) {
        float4 v = x[i];
        s += v.x * v.x + v.y * v.y + v.z * v.z + v.w * v.w;
    }
    g_sq[pt] = s;
}

// ---------------- kNN on 64-dim x1 (f32x2 dot products) ----------------
__global__ void __launch_bounds__(256) knn64_k(int* __restrict__ idx) {
    __shared__ __align__(16) float4 sq4[128 * 16];
    __shared__ float  ssn[128];
    int b = blockIdx.x >> 3;
    int p = ((blockIdx.x & 7) << 8) + threadIdx.x;
    int pt = (b << 11) + p;
    ulonglong2 xpv[16];
#pragma unroll
    for (int i = 0; i < 16; i++)
        xpv[i] = *reinterpret_cast<const ulonglong2*>(&g_X12[(size_t)pt * 192 + i * 4]);
    float sqp = g_sq[pt];
    float bd[KN]; int bi[KN];
#pragma unroll
    for (int k = 0; k < KN; k++) { bd[k] = 1e30f; bi[k] = 0; }
    for (int q0 = 0; q0 < Pk; q0 += 128) {
        __syncthreads();
        for (int t = threadIdx.x; t < 128 * 16; t += 256) {
            int qr = t >> 4, d4 = t & 15;
            sq4[qr * 16 + d4] = *reinterpret_cast<const float4*>(
                &g_X12[(size_t)((b << 11) + q0 + qr) * 192 + d4 * 4]);
        }
        if (threadIdx.x < 128) ssn[threadIdx.x] = g_sq[(b << 11) + q0 + threadIdx.x];
        __syncthreads();
        for (int qr = 0; qr < 128; qr++) {
            const ulonglong2* qv = reinterpret_cast<const ulonglong2*>(&sq4[qr * 16]);
            u64 d0 = 0ull, d1 = 0ull;
#pragma unroll
            for (int i = 0; i < 16; i++) {
                ulonglong2 q = qv[i];
                fma2(d0, xpv[i].x, q.x);
                fma2(d1, xpv[i].y, q.y);
            }
            float2 f0 = unpack2(d0), f1 = unpack2(d1);
            float dot = (f0.x + f0.y) + (f1.x + f1.y);
            float d = sqp + ssn[qr] - 2.f * dot;
            if (d < bd[KN - 1]) knn_insert(d, q0 + qr, bd, bi);
        }
    }
    int o = pt * KN;
#pragma unroll
    for (int k = 0; k < KN; k++) idx[o + k] = bi[k];
}

// ---------------- EdgeConv2: gather(128) + GEMM 128->128, ReLU, f32x2 --------
__global__ void __launch_bounds__(256) ec2_k(const float* __restrict__ X,
                                             const int* __restrict__ idx,
                                             const float* __restrict__ w,
                                             const float* __restrict__ bias,
                                             float* __restrict__ Z) {
    __shared__ __align__(16) float At[128 * 68];
    __shared__ __align__(16) float Bs[16 * 132];
    int e0 = blockIdx.x * 64;
    for (int i = threadIdx.x; i < 64 * 128; i += 256) {
        int r = i >> 7, col = i & 127;
        int e = e0 + r;
        int pt = e / KN;
        int bb = pt >> 11;
        int j  = idx[e];
        const float* xi = X + (size_t)pt * 192;
        const float* xj = X + ((size_t)(bb << 11) + j) * 192;
        float v = (col < 64) ? xi[col] : (xj[col - 64] - xi[col - 64]);
        At[col * 68 + r] = v;
    }
    int r0 = (threadIdx.x >> 4) * 4;
    int c0 = (threadIdx.x & 15) * 8;
    u64 acc2[4][4] = {};
    for (int kc = 0; kc < 8; kc++) {
        __syncthreads();
        for (int i = threadIdx.x; i < 16 * 128; i += 256) {
            int kk = i >> 7, c = i & 127;
            Bs[kk * 132 + c] = w[(size_t)(kc * 16 + kk) * 128 + c];
        }
        __syncthreads();
#pragma unroll
        for (int kk = 0; kk < 16; kk++) {
            float4 a = *reinterpret_cast<const float4*>(&At[(kc * 16 + kk) * 68 + r0]);
            u64 b0 = *reinterpret_cast<const u64*>(&Bs[kk * 132 + c0]);
            u64 b1 = *reinterpret_cast<const u64*>(&Bs[kk * 132 + c0 + 2]);
            u64 b2 = *reinterpret_cast<const u64*>(&Bs[kk * 132 + c0 + 4]);
            u64 b3 = *reinterpret_cast<const u64*>(&Bs[kk * 132 + c0 + 6]);
            float aa[4] = {a.x, a.y, a.z, a.w};
#pragma unroll
            for (int ii = 0; ii < 4; ii++) {
                u64 ad = pack2(aa[ii], aa[ii]);
                fma2(acc2[ii][0], ad, b0);
                fma2(acc2[ii][1], ad, b1);
                fma2(acc2[ii][2], ad, b2);
                fma2(acc2[ii][3], ad, b3);
            }
        }
    }
    float bv[8];
#pragma unroll
    for (int jj = 0; jj < 8; jj++) bv[jj] = bias[c0 + jj];
#pragma unroll
    for (int ii = 0; ii < 4; ii++) {
        float2 p0 = unpack2(acc2[ii][0]);
        float2 p1 = unpack2(acc2[ii][1]);
        float2 p2 = unpack2(acc2[ii][2]);
        float2 p3 = unpack2(acc2[ii][3]);
        float4 o0, o1;
        o0.x = fmaxf(p0.x + bv[0], 0.f);
        o0.y = fmaxf(p0.y + bv[1], 0.f);
        o0.z = fmaxf(p1.x + bv[2], 0.f);
        o0.w = fmaxf(p1.y + bv[3], 0.f);
        o1.x = fmaxf(p2.x + bv[4], 0.f);
        o1.y = fmaxf(p2.y + bv[5], 0.f);
        o1.z = fmaxf(p3.x + bv[6], 0.f);
        o1.w = fmaxf(p3.y + bv[7], 0.f);
        size_t off = (size_t)(e0 + r0 + ii) * 128 + c0;
        *reinterpret_cast<float4*>(&Z[off])     = o0;
        *reinterpret_cast<float4*>(&Z[off + 4]) = o1;
    }
}

// ---------------- init pool accumulator ----------------
__global__ void initP1_k() {
    int g = blockIdx.x * 256 + threadIdx.x;
    if (g < 16 * 1024) g_P1raw[g] = 0;
}

// ------- fused l1: GEMM 192->1024 + ReLU + stats partials + max pool --------
__global__ void __launch_bounds__(256) l1_k(const float* __restrict__ X,
                                            const float* __restrict__ w,
                                            const float* __restrict__ bias) {
    __shared__ __align__(16) float At[32 * 68];
    __shared__ __align__(16) float Bs[32 * 132];
    __shared__ float red[16 * 128];
    int rb   = blockIdx.x >> 3;
    int row0 = rb * 64;
    int col0 = (blockIdx.x & 7) * 128;
    int bidx = row0 >> 11;                // batch of this row block
    int r0 = (threadIdx.x >> 4) * 4;
    int c0 = (threadIdx.x & 15) * 8;
    u64 acc2[4][4] = {};
    for (int kc = 0; kc < 6; kc++) {
        __syncthreads();
        for (int i = threadIdx.x; i < 64 * 32; i += 256) {
            int r = i >> 5, k = i & 31;
            At[k * 68 + r] = X[(size_t)(row0 + r) * 192 + kc * 32 + k];
        }
        for (int i = threadIdx.x; i < 32 * 128; i += 256) {
            int kk = i >> 7, c = i & 127;
            Bs[kk * 132 + c] = w[(size_t)(kc * 32 + kk) * 1024 + col0 + c];
        }
        __syncthreads();
#pragma unroll
        for (int kk = 0; kk < 32; kk++) {
            float4 a = *reinterpret_cast<const float4*>(&At[kk * 68 + r0]);
            u64 b0 = *reinterpret_cast<const u64*>(&Bs[kk * 132 + c0]);
            u64 b1 = *reinterpret_cast<const u64*>(&Bs[kk * 132 + c0 + 2]);
            u64 b2 = *reinterpret_cast<const u64*>(&Bs[kk * 132 + c0 + 4]);
            u64 b3 = *reinterpret_cast<const u64*>(&Bs[kk * 132 + c0 + 6]);
            float aa[4] = {a.x, a.y, a.z, a.w};
#pragma unroll
            for (int ii = 0; ii < 4; ii++) {
                u64 ad = pack2(aa[ii], aa[ii]);
                fma2(acc2[ii][0], ad, b0);
                fma2(acc2[ii][1], ad, b1);
                fma2(acc2[ii][2], ad, b2);
                fma2(acc2[ii][3], ad, b3);
            }
        }
    }
    // epilogue: relu values in registers (H never materialized)
    float out[4][8];
    float bv[8];
#pragma unroll
    for (int jj = 0; jj < 8; jj++) bv[jj] = bias[col0 + c0 + jj];
#pragma unroll
    for (int ii = 0; ii < 4; ii++) {
        float2 p0 = unpack2(acc2[ii][0]);
        float2 p1 = unpack2(acc2[ii][1]);
        float2 p2 = unpack2(acc2[ii][2]);
        float2 p3 = unpack2(acc2[ii][3]);
        out[ii][0] = fmaxf(p0.x + bv[0], 0.f);
        out[ii][1] = fmaxf(p0.y + bv[1], 0.f);
        out[ii][2] = fmaxf(p1.x + bv[2], 0.f);
        out[ii][3] = fmaxf(p1.y + bv[3], 0.f);
        out[ii][4] = fmaxf(p2.x + bv[4], 0.f);
        out[ii][5] = fmaxf(p2.y + bv[5], 0.f);
        out[ii][6] = fmaxf(p3.x + bv[6], 0.f);
        out[ii][7] = fmaxf(p3.y + bv[7], 0.f);
    }
    int rg = threadIdx.x >> 4;   // row group 0..15
    // pass 1: sums
    __syncthreads();
#pragma unroll
    for (int jj = 0; jj < 8; jj++) {
        float s = out[0][jj] + out[1][jj] + out[2][jj] + out[3][jj];
        red[rg * 128 + c0 + jj] = s;
    }
    __syncthreads();
    if (threadIdx.x < 128) {
        float s = 0.f;
#pragma unroll
        for (int m = 0; m < 16; m++) s += red[m * 128 + threadIdx.x];
        g_part[((size_t)rb * 2 + 0) * 1024 + col0 + threadIdx.x] = s;
    }
    // pass 2: sumsq
    __syncthreads();
#pragma unroll
    for (int jj = 0; jj < 8; jj++) {
        float s = out[0][jj] * out[0][jj] + out[1][jj] * out[1][jj]
                + out[2][jj] * out[2][jj] + out[3][jj] * out[3][jj];
        red[rg * 128 + c0 + jj] = s;
    }
    __syncthreads();
    if (threadIdx.x < 128) {
        float s = 0.f;
#pragma unroll
        for (int m = 0; m < 16; m++) s += red[m * 128 + threadIdx.x];
        g_part[((size_t)rb * 2 + 1) * 1024 + col0 + threadIdx.x] = s;
    }
    // pass 3: max -> atomicMax (values >= 0, int-bit compare == float compare)
    __syncthreads();
#pragma unroll
    for (int jj = 0; jj < 8; jj++) {
        float m = fmaxf(fmaxf(out[0][jj], out[1][jj]), fmaxf(out[2][jj], out[3][jj]));
        red[rg * 128 + c0 + jj] = m;
    }
    __syncthreads();
    if (threadIdx.x < 128) {
        float m = red[threadIdx.x];
#pragma unroll
        for (int mm = 1; mm < 16; mm++) m = fmaxf(m, red[mm * 128 + threadIdx.x]);
        atomicMax(&g_P1raw[bidx * 1024 + col0 + threadIdx.x], __float_as_int(m));
    }
}

// ---------------- pool affine ----------------
__global__ void pool_aff_k() {
    int g = blockIdx.x * 256 + threadIdx.x;  // 16*1024
    int c = g & 1023;
    float m = __int_as_float(g_P1raw[g]);
    g_P1[g] = fmaf(g_s5[c], m, g_h5[c]);
}

// ---------------- head ----------------
__global__ void head1_k(const float* __restrict__ w, const float* __restrict__ bias) {
    int g = blockIdx.x * 256 + threadIdx.x;  // 16*512
    int b = g >> 9, c = g & 511;
    float a = bias[c];
    const float* p = g_P1 + (b << 10);
    for (int r = 0; r < 1024; r++) a = fmaf(p[r], w[(size_t)r * 512 + c], a);
    g_Zm1[g] = fmaxf(a, 0.f);
}

__global__ void stats16_k(const float* __restrict__ Z, int C,
                          const float* __restrict__ g, const float* __restrict__ be,
                          float* __restrict__ scale, float* __restrict__ shift) {
    int c = blockIdx.x * blockDim.x + threadIdx.x;
    if (c >= C) return;
    float s = 0.f, q = 0.f;
    for (int b = 0; b < 16; b++) { float v = Z[b * C + c]; s += v; q += v * v; }
    float mean = s * (1.f / 16.f);
    float var  = q * (1.f / 16.f) - mean * mean;
    float sc = g[c] * rsqrtf(var + EPSB);
    scale[c] = sc;
    shift[c] = be[c] - mean * sc;
}

__global__ void head2_k(const float* __restrict__ w) {
    int g = blockIdx.x * 256 + threadIdx.x;  // 16*256
    int b = g >> 8, c = g & 255;
    float a = g_ebm2[c];
    const float* z = g_Zm1 + b * 512;
    for (int r = 0; r < 512; r++) a = fmaf(z[r] * g_s6[r], w[(size_t)r * 256 + c], a);
    g_Zm2[g] = fmaxf(a, 0.f);
}

__global__ void head3_k(const float* __restrict__ w, float* __restrict__ out) {
    int t = threadIdx.x;
    if (t >= 32) return;
    int b = t >> 1, n = t & 1;
    float a = g_ebm3[n];
    const float* z = g_Zm2 + b * 256;
    for (int r = 0; r < 256; r++) a = fmaf(z[r] * g_s7[r], w[r * 2 + n], a);
    out[b * 2 + n] = a;
}

// ---------------- launch ----------------
extern "C" void kernel_launch(void* const* d_in, const int* in_sizes, int n_in,
                              void* d_out, int out_size) {
    const float* pos  = (const float*)d_in[0];
    const float* c1w0 = (const float*)d_in[1];
    const float* c1b0 = (const float*)d_in[2];
    const float* c1g0 = (const float*)d_in[3];
    const float* c1e0 = (const float*)d_in[4];
    const float* c1w1 = (const float*)d_in[5];
    const float* c1b1 = (const float*)d_in[6];
    const float* c1g1 = (const float*)d_in[7];
    const float* c1e1 = (const float*)d_in[8];
    const float* c1w2 = (const float*)d_in[9];
    const float* c1b2 = (const float*)d_in[10];
    const float* c1g2 = (const float*)d_in[11];
    const float* c1e2 = (const float*)d_in[12];
    const float* c2w  = (const float*)d_in[13];
    const float* c2b  = (const float*)d_in[14];
    const float* c2g  = (const float*)d_in[15];
    const float* c2e  = (const float*)d_in[16];
    const float* l1w  = (const float*)d_in[17];
    const float* l1b  = (const float*)d_in[18];
    const float* l1g  = (const float*)d_in[19];
    const float* l1e  = (const float*)d_in[20];
    const float* m1w  = (const float*)d_in[21];
    const float* m1b  = (const float*)d_in[22];
    const float* m1g  = (const float*)d_in[23];
    const float* m1e  = (const float*)d_in[24];
    const float* m2w  = (const float*)d_in[25];
    const float* m2b  = (const float*)d_in[26];
    const float* m2g  = (const float*)d_in[27];
    const float* m2e  = (const float*)d_in[28];
    const float* m3w  = (const float*)d_in[29];
    const float* m3b  = (const float*)d_in[30];

    void *pZ1, *pZ2, *pZ4, *pX, *pI1, *pI2;
    void *ps1, *ph1, *ps2, *ph2, *ps3, *ph3, *ps4, *ph4, *ps5, *ph5, *ps6, *ph6, *ps7, *ph7;
    void *peb2, *peb3, *pebm2, *pebm3, *pZm1, *pZm2;
    cudaGetSymbolAddress(&pZ1, g_Z1);
    cudaGetSymbolAddress(&pZ2, g_Z2);
    cudaGetSymbolAddress(&pZ4, g_Z4);
    cudaGetSymbolAddress(&pX,  g_X12);
    cudaGetSymbolAddress(&pI1, g_idx1);
    cudaGetSymbolAddress(&pI2, g_idx2);
    cudaGetSymbolAddress(&ps1, g_s1); cudaGetSymbolAddress(&ph1, g_h1);
    cudaGetSymbolAddress(&ps2, g_s2); cudaGetSymbolAddress(&ph2, g_h2);
    cudaGetSymbolAddress(&ps3, g_s3); cudaGetSymbolAddress(&ph3, g_h3);
    cudaGetSymbolAddress(&ps4, g_s4); cudaGetSymbolAddress(&ph4, g_h4);
    cudaGetSymbolAddress(&ps5, g_s5); cudaGetSymbolAddress(&ph5, g_h5);
    cudaGetSymbolAddress(&ps6, g_s6); cudaGetSymbolAddress(&ph6, g_h6);
    cudaGetSymbolAddress(&ps7, g_s7); cudaGetSymbolAddress(&ph7, g_h7);
    cudaGetSymbolAddress(&peb2, g_eb2); cudaGetSymbolAddress(&peb3, g_eb3);
    cudaGetSymbolAddress(&pebm2, g_ebm2); cudaGetSymbolAddress(&pebm3, g_ebm3);
    cudaGetSymbolAddress(&pZm1, g_Zm1); cudaGetSymbolAddress(&pZm2, g_Zm2);

    float* Z1 = (float*)pZ1;  float* Z2 = (float*)pZ2;  float* Z4 = (float*)pZ4;
    float* X  = (float*)pX;
    int* I1 = (int*)pI1;      int* I2 = (int*)pI2;

    // --- EdgeConv1 ---
    knn3_k<<<128, 256>>>(pos, I1);
    ec1_l0_k<<<NEDG * 4 / 256, 256>>>(pos, I1, c1w0, c1b0, Z1);
    stats_k<64><<<NBLK, 256>>>(Z1, NEDG / NBLK);
    finalize_k<<<8, 256>>>(64, (float)NEDG, NBLK, c1g0, c1e0, (float*)ps1, (float*)ph1);
    foldbias_k<<<1, 64>>>(64, 64, c1w1, c1b1, (float*)ph1, (float*)peb2);
    ec_mid_k<<<NEDG / 64, 256>>>(Z1, c1w1, (float*)ps1, (float*)peb2, Z2);
    stats_k<64><<<NBLK, 256>>>(Z2, NEDG / NBLK);
    finalize_k<<<8, 256>>>(64, (float)NEDG, NBLK, c1g1, c1e1, (float*)ps2, (float*)ph2);
    foldbias_k<<<1, 64>>>(64, 64, c1w2, c1b2, (float*)ph2, (float*)peb3);
    ec_mid_k<<<NEDG / 64, 256>>>(Z2, c1w2, (float*)ps2, (float*)peb3, Z1);
    stats_k<64><<<NBLK, 256>>>(Z1, NEDG / NBLK);
    finalize_k<<<8, 256>>>(64, (float)NEDG, NBLK, c1g2, c1e2, (float*)ps3, (float*)ph3);
    maxE_k<<<NPTS * 16 / 256, 256>>>(Z1, 64, (float*)ps3, (float*)ph3, X, 0);

    // --- EdgeConv2 ---
    sqnorm_k<<<NPTS / 256, 256>>>();
    knn64_k<<<128, 256>>>(I2);
    ec2_k<<<NEDG / 64, 256>>>(X, I2, c2w, c2b, Z4);
    stats_k<128><<<NBLK, 256>>>(Z4, NEDG / NBLK);
    finalize_k<<<16, 256>>>(128, (float)NEDG, NBLK, c2g, c2e, (float*)ps4, (float*)ph4);
    maxE_k<<<NPTS * 32 / 256, 256>>>(Z4, 128, (float*)ps4, (float*)ph4, X, 64);

    // --- fused l1 (GEMM + stats partials + max pool) ---
    initP1_k<<<64, 256>>>();
    l1_k<<<HRB * 8, 256>>>(X, l1w, l1b);
    finalize_k<<<128, 256>>>(1024, (float)NPTS, HRB, l1g, l1e, (float*)ps5, (float*)ph5);
    pool_aff_k<<<64, 256>>>();

    // --- head ---
    head1_k<<<32, 256>>>(m1w, m1b);
    stats16_k<<<2, 256>>>((float*)pZm1, 512, m1g, m1e, (float*)ps6, (float*)ph6);
    foldbias_k<<<1, 256>>>(512, 256, m2w, m2b, (float*)ph6, (float*)pebm2);
    head2_k<<<16, 256>>>(m2w);
    stats16_k<<<1, 256>>>((float*)pZm2, 256, m2g, m2e, (float*)ps7, (float*)ph7);
    foldbias_k<<<1, 32>>>(256, 2, m3w, m3b, (float*)ph7, (float*)pebm3);
    head3_k<<<1, 32>>>(m3w, (float*)d_out);
}

// round 4
// speedup vs baseline: 1.3110x; 1.0012x over previous
#include <cuda_runtime.h>
#include <cuda_bf16.h>
#include <cstddef>

// ---------------- problem constants ----------------
#define EPSB 1e-5f
constexpr int Bk   = 16;
constexpr int Pk   = 2048;
constexpr int KN   = 5;
constexpr int NPTS = Bk * Pk;       // 32768
constexpr int NEDG = NPTS * KN;     // 163840
constexpr int NBLK = 256;           // stat partial blocks (edge tensors)
constexpr int HRB  = NPTS / 64;     // 512 row-blocks for fused l1 stats

using u64 = unsigned long long;

// ---------------- scratch (device globals; no runtime allocation) ----------
__device__ float g_Z1[(size_t)NEDG * 64];
__device__ float g_Z2[(size_t)NEDG * 64];
__device__ float g_Z4[(size_t)NEDG * 128];
__device__ float g_X12[(size_t)NPTS * 192];   // cols 0..63 = x1, 64..191 = x2
__device__ float g_sq[NPTS];
__device__ int   g_idx1[NEDG];
__device__ int   g_idx2[NEDG];
__device__ float g_bd2[(size_t)NPTS * 10];    // split-kNN partial dists
__device__ int   g_bi2[(size_t)NPTS * 10];    // split-kNN partial indices
__device__ float g_part[(size_t)HRB * 2 * 1024];
__device__ float g_s1[64],  g_h1[64];
__device__ float g_s2[64],  g_h2[64];
__device__ float g_s3[64],  g_h3[64];
__device__ float g_s4[128], g_h4[128];
__device__ float g_s5[1024],g_h5[1024];
__device__ float g_s6[512], g_h6[512];
__device__ float g_s7[256], g_h7[256];
__device__ float g_eb2[64], g_eb3[64], g_ebm2[256], g_ebm3[2];
__device__ int   g_P1raw[16 * 1024];
__device__ float g_Zm1[16 * 512];
__device__ float g_Zm2[16 * 256];

// ---------------- f32x2 packed-FMA helpers ----------------
__device__ __forceinline__ u64 pack2(float lo, float hi) {
    u64 r; asm("mov.b64 %0, {%1, %2};" : "=l"(r) : "f"(lo), "f"(hi)); return r;
}
__device__ __forceinline__ float2 unpack2(u64 v) {
    float2 r; asm("mov.b64 {%0, %1}, %2;" : "=f"(r.x), "=f"(r.y) : "l"(v)); return r;
}
__device__ __forceinline__ void fma2(u64& d, u64 a, u64 b) {
    asm("fma.rn.f32x2 %0, %1, %2, %0;" : "+l"(d) : "l"(a), "l"(b));
}

// ---------------- helpers ----------------
__device__ __forceinline__ void knn_insert(float d, int j, float bd[KN], int bi[KN]) {
#pragma unroll
    for (int k = 0; k < KN; k++) {
        if (d < bd[k]) {
            float td = bd[k]; int ti = bi[k];
            bd[k] = d; bi[k] = j;
            d = td; j = ti;
        }
    }
}

// ---------------- kNN on positions (D=3) ----------------
__global__ void knn3_k(const float* __restrict__ pos, int* __restrict__ idx) {
    __shared__ float sx[Pk], sy[Pk], sz[Pk], sn[Pk];
    int b  = blockIdx.x >> 3;
    int p0 = (blockIdx.x & 7) << 8;
    const float* base = pos + (size_t)b * Pk * 3;
    for (int j = threadIdx.x; j < Pk; j += 256) {
        float x = base[3 * j], y = base[3 * j + 1], z = base[3 * j + 2];
        sx[j] = x; sy[j] = y; sz[j] = z;
        sn[j] = x * x + y * y + z * z;
    }
    __syncthreads();
    int p = p0 + threadIdx.x;
    float x = sx[p], y = sy[p], z = sz[p], sq = sn[p];
    float bd[KN]; int bi[KN];
#pragma unroll
    for (int k = 0; k < KN; k++) { bd[k] = 1e30f; bi[k] = 0; }
    for (int j = 0; j < Pk; j++) {
        float dot = x * sx[j] + y * sy[j] + z * sz[j];
        float d = sq + sn[j] - 2.f * dot;
        if (d < bd[KN - 1]) knn_insert(d, j, bd, bi);
    }
    int o = (b * Pk + p) * KN;
#pragma unroll
    for (int k = 0; k < KN; k++) idx[o + k] = bi[k];
}

// ---------------- EdgeConv1 layer0: edges(6) -> 64, ReLU ----------------
__global__ void ec1_l0_k(const float* __restrict__ pos, const int* __restrict__ idx,
                         const float* __restrict__ w, const float* __restrict__ bias,
                         float* __restrict__ Z) {
    __shared__ float sw[6 * 64];
    __shared__ float sb[64];
    if (threadIdx.x < 64) sb[threadIdx.x] = bias[threadIdx.x];
    for (int i = threadIdx.x; i < 384; i += 256) sw[i] = w[i];
    __syncthreads();
    int g = blockIdx.x * 256 + threadIdx.x;
    int e = g >> 2, q = g & 3;
    int pt = e / KN;
    int b  = pt >> 11;
    int j  = idx[e];
    const float* pi = pos + (size_t)pt * 3;
    const float* pj = pos + ((size_t)(b << 11) + j) * 3;
    float e0 = pi[0], e1 = pi[1], e2 = pi[2];
    float e3 = pj[0] - e0, e4 = pj[1] - e1, e5 = pj[2] - e2;
    int c0 = q * 16;
    float out[16];
#pragma unroll
    for (int c = 0; c < 16; c++) {
        int cc = c0 + c;
        float a = sb[cc];
        a = fmaf(e0, sw[0 * 64 + cc], a);
        a = fmaf(e1, sw[1 * 64 + cc], a);
        a = fmaf(e2, sw[2 * 64 + cc], a);
        a = fmaf(e3, sw[3 * 64 + cc], a);
        a = fmaf(e4, sw[4 * 64 + cc], a);
        a = fmaf(e5, sw[5 * 64 + cc], a);
        out[c] = fmaxf(a, 0.f);
    }
    float4* dst = reinterpret_cast<float4*>(Z + (size_t)e * 64 + c0);
#pragma unroll
    for (int v = 0; v < 4; v++)
        dst[v] = make_float4(out[v * 4], out[v * 4 + 1], out[v * 4 + 2], out[v * 4 + 3]);
}

// ---------------- per-channel stats partials (deterministic) ----------------
template <int C>
__global__ void stats_k(const float* __restrict__ Z, int rpb) {
    __shared__ float ssum[256], ssq[256];
    int row0 = blockIdx.x * rpb;
    if (C >= 256) {
#pragma unroll
        for (int m = 0; m < C / 256; m++) {
            int c = threadIdx.x + m * 256;
            float s = 0.f, q = 0.f;
            for (int r = 0; r < rpb; r++) {
                float v = Z[(size_t)(row0 + r) * C + c];
                s += v; q += v * v;
            }
            g_part[((size_t)blockIdx.x * 2 + 0) * C + c] = s;
            g_part[((size_t)blockIdx.x * 2 + 1) * C + c] = q;
        }
    } else {
        const int ns = 256 / C;
        int c  = threadIdx.x % C;
        int sl = threadIdx.x / C;
        int rs = rpb / ns;
        float s = 0.f, q = 0.f;
        for (int r = sl * rs; r < (sl + 1) * rs; r++) {
            float v = Z[(size_t)(row0 + r) * C + c];
            s += v; q += v * v;
        }
        ssum[threadIdx.x] = s; ssq[threadIdx.x] = q;
        __syncthreads();
        if (sl == 0) {
            for (int m = 1; m < ns; m++) { s += ssum[m * C + c]; q += ssq[m * C + c]; }
            g_part[((size_t)blockIdx.x * 2 + 0) * C + c] = s;
            g_part[((size_t)blockIdx.x * 2 + 1) * C + c] = q;
        }
    }
}

// one warp per channel, parallel over partial blocks
__global__ void finalize_k(int C, float n, int nblk, const float* __restrict__ g,
                           const float* __restrict__ be,
                           float* __restrict__ scale, float* __restrict__ shift) {
    int warp = (blockIdx.x * blockDim.x + threadIdx.x) >> 5;
    int lane = threadIdx.x & 31;
    if (warp >= C) return;
    float s = 0.f, q = 0.f;
    for (int b = lane; b < nblk; b += 32) {
        s += g_part[((size_t)b * 2 + 0) * C + warp];
        q += g_part[((size_t)b * 2 + 1) * C + warp];
    }
#pragma unroll
    for (int o = 16; o; o >>= 1) {
        s += __shfl_xor_sync(0xffffffffu, s, o);
        q += __shfl_xor_sync(0xffffffffu, q, o);
    }
    if (lane == 0) {
        float mean = s / n;
        float var  = q / n - mean * mean;
        float sc = g[warp] * rsqrtf(var + EPSB);
        scale[warp] = sc;
        shift[warp] = be[warp] - mean * sc;
    }
}

__global__ void foldbias_k(int Cin, int Cout, const float* __restrict__ w,
                           const float* __restrict__ bias, const float* __restrict__ shift,
                           float* __restrict__ eb) {
    int c = blockIdx.x * blockDim.x + threadIdx.x;
    if (c >= Cout) return;
    float a = bias[c];
    for (int r = 0; r < Cin; r++) a = fmaf(shift[r], w[(size_t)r * Cout + c], a);
    eb[c] = a;
}

// ---------------- 64->64 GEMM (BN-folded input), ReLU, f32x2 ----------------
// warp tile: 16 rows x 32 cols; lane tile 4x4 (rh = lane>>3, ch = lane&7)
__global__ void __launch_bounds__(256) ec_mid_k(const float* __restrict__ Zin,
                                                const float* __restrict__ w,
                                                const float* __restrict__ scaleIn,
                                                const float* __restrict__ eb,
                                                float* __restrict__ Zout) {
    __shared__ __align__(16) float At[64 * 68];
    __shared__ __align__(16) float Bs[64 * 68];
    int row0 = blockIdx.x * 64;
    for (int i = threadIdx.x; i < 64 * 64; i += 256) {
        int r = i >> 6, k = i & 63;
        At[k * 68 + r] = Zin[(size_t)(row0 + r) * 64 + k];
    }
    for (int i = threadIdx.x; i < 64 * 64; i += 256) {
        int k = i >> 6, c = i & 63;
        Bs[k * 68 + c] = scaleIn[k] * w[i];
    }
    __syncthreads();
    int wrp = threadIdx.x >> 5, lane = threadIdx.x & 31;
    int r0 = (wrp >> 1) * 16 + (lane >> 3) * 4;
    int c0 = (wrp & 1) * 32 + (lane & 7) * 4;
    u64 acc2[4][2] = {};
#pragma unroll 4
    for (int k = 0; k < 64; k++) {
        float4 a = *reinterpret_cast<const float4*>(&At[k * 68 + r0]);
        ulonglong2 bv = *reinterpret_cast<const ulonglong2*>(&Bs[k * 68 + c0]);
        float aa[4] = {a.x, a.y, a.z, a.w};
#pragma unroll
        for (int ii = 0; ii < 4; ii++) {
            u64 ad = pack2(aa[ii], aa[ii]);
            fma2(acc2[ii][0], ad, bv.x);
            fma2(acc2[ii][1], ad, bv.y);
        }
    }
    float e0 = eb[c0], e1 = eb[c0 + 1], e2 = eb[c0 + 2], e3 = eb[c0 + 3];
#pragma unroll
    for (int ii = 0; ii < 4; ii++) {
        float2 p0 = unpack2(acc2[ii][0]);
        float2 p1 = unpack2(acc2[ii][1]);
        float4 o;
        o.x = fmaxf(p0.x + e0, 0.f);
        o.y = fmaxf(p0.y + e1, 0.f);
        o.z = fmaxf(p1.x + e2, 0.f);
        o.w = fmaxf(p1.y + e3, 0.f);
        *reinterpret_cast<float4*>(&Zout[(size_t)(row0 + r0 + ii) * 64 + c0]) = o;
    }
}

// -------- k-max over edges + BN affine (+ optional fused sqnorm) --------
__global__ void maxE_k(const float* __restrict__ Z, int C,
                       const float* __restrict__ scale, const float* __restrict__ shift,
                       float* __restrict__ X, int colOff, int doSq) {
    int g = blockIdx.x * 256 + threadIdx.x;
    int per = C >> 2;
    int pt = g / per;
    int c4 = (g % per) * 4;
    float4 m = make_float4(-1e30f, -1e30f, -1e30f, -1e30f);
#pragma unroll
    for (int k = 0; k < KN; k++) {
        float4 v = *reinterpret_cast<const float4*>(&Z[(size_t)(pt * KN + k) * C + c4]);
        m.x = fmaxf(m.x, v.x); m.y = fmaxf(m.y, v.y);
        m.z = fmaxf(m.z, v.z); m.w = fmaxf(m.w, v.w);
    }
    float4 o;
    o.x = fmaf(scale[c4 + 0], m.x, shift[c4 + 0]);
    o.y = fmaf(scale[c4 + 1], m.y, shift[c4 + 1]);
    o.z = fmaf(scale[c4 + 2], m.z, shift[c4 + 2]);
    o.w = fmaf(scale[c4 + 3], m.w, shift[c4 + 3]);
    *reinterpret_cast<float4*>(&X[(size_t)pt * 192 + colOff + c4]) = o;
    if (doSq) {   // C==64 path: 16 consecutive lanes hold one point
        float s = o.x * o.x + o.y * o.y + o.z * o.z + o.w * o.w;
#pragma unroll
        for (int off = 8; off; off >>= 1)
            s += __shfl_down_sync(0xffffffffu, s, off, 16);
        if ((threadIdx.x & 15) == 0) g_sq[pt] = s;
    }
}

// ------- kNN on 64-dim x1, candidate-split (half per block), f32x2 ---------
__global__ void __launch_bounds__(256) knn64_k(float* __restrict__ bd2,
                                               int* __restrict__ bi2) {
    __shared__ __align__(16) float4 sq4[128 * 16];
    __shared__ float  ssn[128];
    int half = blockIdx.x & 1;
    int grp  = blockIdx.x >> 1;
    int b = grp >> 3;
    int p = ((grp & 7) << 8) + threadIdx.x;
    int pt = (b << 11) + p;
    ulonglong2 xpv[16];
#pragma unroll
    for (int i = 0; i < 16; i++)
        xpv[i] = *reinterpret_cast<const ulonglong2*>(&g_X12[(size_t)pt * 192 + i * 4]);
    float sqp = g_sq[pt];
    float bd[KN]; int bi[KN];
#pragma unroll
    for (int k = 0; k < KN; k++) { bd[k] = 1e30f; bi[k] = 0; }
    int qbase = half << 10;
    for (int q0 = qbase; q0 < qbase + 1024; q0 += 128) {
        __syncthreads();
        for (int t = threadIdx.x; t < 128 * 16; t += 256) {
            int qr = t >> 4, d4 = t & 15;
            sq4[qr * 16 + d4] = *reinterpret_cast<const float4*>(
                &g_X12[(size_t)((b << 11) + q0 + qr) * 192 + d4 * 4]);
        }
        if (threadIdx.x < 128) ssn[threadIdx.x] = g_sq[(b << 11) + q0 + threadIdx.x];
        __syncthreads();
        for (int qr = 0; qr < 128; qr++) {
            const ulonglong2* qv = reinterpret_cast<const ulonglong2*>(&sq4[qr * 16]);
            u64 dc[4] = {};
#pragma unroll
            for (int i = 0; i < 16; i += 2) {
                ulonglong2 qa = qv[i], qb = qv[i + 1];
                fma2(dc[0], xpv[i].x, qa.x);
                fma2(dc[1], xpv[i].y, qa.y);
                fma2(dc[2], xpv[i + 1].x, qb.x);
                fma2(dc[3], xpv[i + 1].y, qb.y);
            }
            float2 f0 = unpack2(dc[0]), f1 = unpack2(dc[1]);
            float2 f2 = unpack2(dc[2]), f3 = unpack2(dc[3]);
            float dot = ((f0.x + f0.y) + (f1.x + f1.y)) + ((f2.x + f2.y) + (f3.x + f3.y));
            float d = sqp + ssn[qr] - 2.f * dot;
            if (d < bd[KN - 1]) knn_insert(d, q0 + qr, bd, bi);
        }
    }
    size_t o = (size_t)pt * 10 + half * 5;
#pragma unroll
    for (int k = 0; k < KN; k++) { bd2[o + k] = bd[k]; bi2[o + k] = bi[k]; }
}

// merge two sorted 5-lists per point (list0 has lower indices -> wins ties)
__global__ void knnmerge_k(const float* __restrict__ bd2, const int* __restrict__ bi2,
                           int* __restrict__ idx) {
    int pt = blockIdx.x * 256 + threadIdx.x;
    const float* d0 = bd2 + (size_t)pt * 10;
    const float* d1 = d0 + 5;
    const int*   i0 = bi2 + (size_t)pt * 10;
    const int*   i1 = i0 + 5;
    int a = 0, c = 0;
#pragma unroll
    for (int k = 0; k < KN; k++) {
        bool take0 = (c >= KN) || (a < KN && d0[a] <= d1[c]);
        idx[pt * KN + k] = take0 ? i0[a] : i1[c];
        if (take0) a++; else c++;
    }
}

// ---------------- EdgeConv2: gather(128) + GEMM 128->128, ReLU, f32x2 --------
// warp tile: 16 rows x 64 cols; lane tile 4x8
__global__ void __launch_bounds__(256) ec2_k(const float* __restrict__ X,
                                             const int* __restrict__ idx,
                                             const float* __restrict__ w,
                                             const float* __restrict__ bias,
                                             float* __restrict__ Z) {
    __shared__ __align__(16) float At[128 * 68];
    __shared__ __align__(16) float Bs[16 * 132];
    int e0 = blockIdx.x * 64;
    for (int i = threadIdx.x; i < 64 * 128; i += 256) {
        int r = i >> 7, col = i & 127;
        int e = e0 + r;
        int pt = e / KN;
        int bb = pt >> 11;
        int j  = idx[e];
        const float* xi = X + (size_t)pt * 192;
        const float* xj = X + ((size_t)(bb << 11) + j) * 192;
        float v = (col < 64) ? xi[col] : (xj[col - 64] - xi[col - 64]);
        At[col * 68 + r] = v;
    }
    int wrp = threadIdx.x >> 5, lane = threadIdx.x & 31;
    int r0 = (wrp >> 1) * 16 + (lane >> 3) * 4;
    int c0 = (wrp & 1) * 64 + (lane & 7) * 8;
    u64 acc2[4][4] = {};
    for (int kc = 0; kc < 8; kc++) {
        __syncthreads();
        for (int i = threadIdx.x; i < 16 * 128; i += 256) {
            int kk = i >> 7, c = i & 127;
            Bs[kk * 132 + c] = w[(size_t)(kc * 16 + kk) * 128 + c];
        }
        __syncthreads();
#pragma unroll
        for (int kk = 0; kk < 16; kk++) {
            float4 a = *reinterpret_cast<const float4*>(&At[(kc * 16 + kk) * 68 + r0]);
            ulonglong2 b01 = *reinterpret_cast<const ulonglong2*>(&Bs[kk * 132 + c0]);
            ulonglong2 b23 = *reinterpret_cast<const ulonglong2*>(&Bs[kk * 132 + c0 + 4]);
            float aa[4] = {a.x, a.y, a.z, a.w};
#pragma unroll
            for (int ii = 0; ii < 4; ii++) {
                u64 ad = pack2(aa[ii], aa[ii]);
                fma2(acc2[ii][0], ad, b01.x);
                fma2(acc2[ii][1], ad, b01.y);
                fma2(acc2[ii][2], ad, b23.x);
                fma2(acc2[ii][3], ad, b23.y);
            }
        }
    }
    float bv[8];
#pragma unroll
    for (int jj = 0; jj < 8; jj++) bv[jj] = bias[c0 + jj];
#pragma unroll
    for (int ii = 0; ii < 4; ii++) {
        float2 p0 = unpack2(acc2[ii][0]);
        float2 p1 = unpack2(acc2[ii][1]);
        float2 p2 = unpack2(acc2[ii][2]);
        float2 p3 = unpack2(acc2[ii][3]);
        float4 o0, o1;
        o0.x = fmaxf(p0.x + bv[0], 0.f);
        o0.y = fmaxf(p0.y + bv[1], 0.f);
        o0.z = fmaxf(p1.x + bv[2], 0.f);
        o0.w = fmaxf(p1.y + bv[3], 0.f);
        o1.x = fmaxf(p2.x + bv[4], 0.f);
        o1.y = fmaxf(p2.y + bv[5], 0.f);
        o1.z = fmaxf(p3.x + bv[6], 0.f);
        o1.w = fmaxf(p3.y + bv[7], 0.f);
        size_t off = (size_t)(e0 + r0 + ii) * 128 + c0;
        *reinterpret_cast<float4*>(&Z[off])     = o0;
        *reinterpret_cast<float4*>(&Z[off + 4]) = o1;
    }
}

// ---------------- init pool accumulator ----------------
__global__ void initP1_k() {
    int g = blockIdx.x * 256 + threadIdx.x;
    if (g < 16 * 1024) g_P1raw[g] = 0;
}

// ------- fused l1: GEMM 192->1024 + ReLU + stats partials + max pool --------
__global__ void __launch_bounds__(256) l1_k(const float* __restrict__ X,
                                            const float* __restrict__ w,
                                            const float* __restrict__ bias) {
    __shared__ __align__(16) float At[32 * 68];
    __shared__ __align__(16) float Bs[32 * 132];
    __shared__ float red[16 * 128];
    int rb   = blockIdx.x >> 3;
    int row0 = rb * 64;
    int col0 = (blockIdx.x & 7) * 128;
    int bidx = row0 >> 11;
    int wrp = threadIdx.x >> 5, lane = threadIdx.x & 31;
    int r0 = (wrp >> 1) * 16 + (lane >> 3) * 4;
    int c0 = (wrp & 1) * 64 + (lane & 7) * 8;
    u64 acc2[4][4] = {};
    for (int kc = 0; kc < 6; kc++) {
        __syncthreads();
        for (int i = threadIdx.x; i < 64 * 32; i += 256) {
            int r = i >> 5, k = i & 31;
            At[k * 68 + r] = X[(size_t)(row0 + r) * 192 + kc * 32 + k];
        }
        for (int i = threadIdx.x; i < 32 * 128; i += 256) {
            int kk = i >> 7, c = i & 127;
            Bs[kk * 132 + c] = w[(size_t)(kc * 32 + kk) * 1024 + col0 + c];
        }
        __syncthreads();
#pragma unroll
        for (int kk = 0; kk < 32; kk++) {
            float4 a = *reinterpret_cast<const float4*>(&At[kk * 68 + r0]);
            ulonglong2 b01 = *reinterpret_cast<const ulonglong2*>(&Bs[kk * 132 + c0]);
            ulonglong2 b23 = *reinterpret_cast<const ulonglong2*>(&Bs[kk * 132 + c0 + 4]);
            float aa[4] = {a.x, a.y, a.z, a.w};
#pragma unroll
            for (int ii = 0; ii < 4; ii++) {
                u64 ad = pack2(aa[ii], aa[ii]);
                fma2(acc2[ii][0], ad, b01.x);
                fma2(acc2[ii][1], ad, b01.y);
                fma2(acc2[ii][2], ad, b23.x);
                fma2(acc2[ii][3], ad, b23.y);
            }
        }
    }
    float out[4][8];
    float bv[8];
#pragma unroll
    for (int jj = 0; jj < 8; jj++) bv[jj] = bias[col0 + c0 + jj];
#pragma unroll
    for (int ii = 0; ii < 4; ii++) {
        float2 p0 = unpack2(acc2[ii][0]);
        float2 p1 = unpack2(acc2[ii][1]);
        float2 p2 = unpack2(acc2[ii][2]);
        float2 p3 = unpack2(acc2[ii][3]);
        out[ii][0] = fmaxf(p0.x + bv[0], 0.f);
        out[ii][1] = fmaxf(p0.y + bv[1], 0.f);
        out[ii][2] = fmaxf(p1.x + bv[2], 0.f);
        out[ii][3] = fmaxf(p1.y + bv[3], 0.f);
        out[ii][4] = fmaxf(p2.x + bv[4], 0.f);
        out[ii][5] = fmaxf(p2.y + bv[5], 0.f);
        out[ii][6] = fmaxf(p3.x + bv[6], 0.f);
        out[ii][7] = fmaxf(p3.y + bv[7], 0.f);
    }
    int rg = (wrp >> 1) * 4 + (lane >> 3);   // row group 0..15
    // pass 1: sums
    __syncthreads();
#pragma unroll
    for (int jj = 0; jj < 8; jj++) {
        float s = out[0][jj] + out[1][jj] + out[2][jj] + out[3][jj];
        red[rg * 128 + c0 + jj] = s;
    }
    __syncthreads();
    if (threadIdx.x < 128) {
        float s = 0.f;
#pragma unroll
        for (int m = 0; m < 16; m++) s += red[m * 128 + threadIdx.x];
        g_part[((size_t)rb * 2 + 0) * 1024 + col0 + threadIdx.x] = s;
    }
    // pass 2: sumsq
    __syncthreads();
#pragma unroll
    for (int jj = 0; jj < 8; jj++) {
        float s = out[0][jj] * out[0][jj] + out[1][jj] * out[1][jj]
                + out[2][jj] * out[2][jj] + out[3][jj] * out[3][jj];
        red[rg * 128 + c0 + jj] = s;
    }
    __syncthreads();
    if (threadIdx.x < 128) {
        float s = 0.f;
#pragma unroll
        for (int m = 0; m < 16; m++) s += red[m * 128 + threadIdx.x];
        g_part[((size_t)rb * 2 + 1) * 1024 + col0 + threadIdx.x] = s;
    }
    // pass 3: max -> atomicMax (values >= 0, int-bit compare == float compare)
    __syncthreads();
#pragma unroll
    for (int jj = 0; jj < 8; jj++) {
        float m = fmaxf(fmaxf(out[0][jj], out[1][jj]), fmaxf(out[2][jj], out[3][jj]));
        red[rg * 128 + c0 + jj] = m;
    }
    __syncthreads();
    if (threadIdx.x < 128) {
        float m = red[threadIdx.x];
#pragma unroll
        for (int mm = 1; mm < 16; mm++) m = fmaxf(m, red[mm * 128 + threadIdx.x]);
        atomicMax(&g_P1raw[bidx * 1024 + col0 + threadIdx.x], __float_as_int(m));
    }
}

// ---------------- head (pool affine fused into head1) ----------------
__global__ void head1_k(const float* __restrict__ w, const float* __restrict__ bias) {
    __shared__ float sp[1024];
    int g = blockIdx.x * 256 + threadIdx.x;  // 16*512
    int b = g >> 9, c = g & 511;
    for (int i = threadIdx.x; i < 1024; i += 256)
        sp[i] = fmaf(g_s5[i], __int_as_float(g_P1raw[(b << 10) + i]), g_h5[i]);
    __syncthreads();
    float a = bias[c];
#pragma unroll 8
    for (int r = 0; r < 1024; r++) a = fmaf(sp[r], w[(size_t)r * 512 + c], a);
    g_Zm1[g] = fmaxf(a, 0.f);
}

__global__ void stats16_k(const float* __restrict__ Z, int C,
                          const float* __restrict__ g, const float* __restrict__ be,
                          float* __restrict__ scale, float* __restrict__ shift) {
    int c = blockIdx.x * blockDim.x + threadIdx.x;
    if (c >= C) return;
    float s = 0.f, q = 0.f;
    for (int b = 0; b < 16; b++) { float v = Z[b * C + c]; s += v; q += v * v; }
    float mean = s * (1.f / 16.f);
    float var  = q * (1.f / 16.f) - mean * mean;
    float sc = g[c] * rsqrtf(var + EPSB);
    scale[c] = sc;
    shift[c] = be[c] - mean * sc;
}

__global__ void head2_k(const float* __restrict__ w) {
    int g = blockIdx.x * 256 + threadIdx.x;  // 16*256
    int b = g >> 8, c = g & 255;
    float a = g_ebm2[c];
    const float* z = g_Zm1 + b * 512;
#pragma unroll 8
    for (int r = 0; r < 512; r++) a = fmaf(z[r] * g_s6[r], w[(size_t)r * 256 + c], a);
    g_Zm2[g] = fmaxf(a, 0.f);
}

__global__ void head3_k(const float* __restrict__ w, float* __restrict__ out) {
    int t = threadIdx.x;
    if (t >= 32) return;
    int b = t >> 1, n = t & 1;
    float a = g_ebm3[n];
    const float* z = g_Zm2 + b * 256;
#pragma unroll 8
    for (int r = 0; r < 256; r++) a = fmaf(z[r] * g_s7[r], w[r * 2 + n], a);
    out[b * 2 + n] = a;
}

// ---------------- launch ----------------
extern "C" void kernel_launch(void* const* d_in, const int* in_sizes, int n_in,
                              void* d_out, int out_size) {
    const float* pos  = (const float*)d_in[0];
    const float* c1w0 = (const float*)d_in[1];
    const float* c1b0 = (const float*)d_in[2];
    const float* c1g0 = (const float*)d_in[3];
    const float* c1e0 = (const float*)d_in[4];
    const float* c1w1 = (const float*)d_in[5];
    const float* c1b1 = (const float*)d_in[6];
    const float* c1g1 = (const float*)d_in[7];
    const float* c1e1 = (const float*)d_in[8];
    const float* c1w2 = (const float*)d_in[9];
    const float* c1b2 = (const float*)d_in[10];
    const float* c1g2 = (const float*)d_in[11];
    const float* c1e2 = (const float*)d_in[12];
    const float* c2w  = (const float*)d_in[13];
    const float* c2b  = (const float*)d_in[14];
    const float* c2g  = (const float*)d_in[15];
    const float* c2e  = (const float*)d_in[16];
    const float* l1w  = (const float*)d_in[17];
    const float* l1b  = (const float*)d_in[18];
    const float* l1g  = (const float*)d_in[19];
    const float* l1e  = (const float*)d_in[20];
    const float* m1w  = (const float*)d_in[21];
    const float* m1b  = (const float*)d_in[22];
    const float* m1g  = (const float*)d_in[23];
    const float* m1e  = (const float*)d_in[24];
    const float* m2w  = (const float*)d_in[25];
    const float* m2b  = (const float*)d_in[26];
    const float* m2g  = (const float*)d_in[27];
    const float* m2e  = (const float*)d_in[28];
    const float* m3w  = (const float*)d_in[29];
    const float* m3b  = (const float*)d_in[30];

    void *pZ1, *pZ2, *pZ4, *pX, *pI1, *pI2, *pBD, *pBI;
    void *ps1, *ph1, *ps2, *ph2, *ps3, *ph3, *ps4, *ph4, *ps5, *ph5, *ps6, *ph6, *ps7, *ph7;
    void *peb2, *peb3, *pebm2, *pebm3, *pZm1, *pZm2;
    cudaGetSymbolAddress(&pZ1, g_Z1);
    cudaGetSymbolAddress(&pZ2, g_Z2);
    cudaGetSymbolAddress(&pZ4, g_Z4);
    cudaGetSymbolAddress(&pX,  g_X12);
    cudaGetSymbolAddress(&pI1, g_idx1);
    cudaGetSymbolAddress(&pI2, g_idx2);
    cudaGetSymbolAddress(&pBD, g_bd2);
    cudaGetSymbolAddress(&pBI, g_bi2);
    cudaGetSymbolAddress(&ps1, g_s1); cudaGetSymbolAddress(&ph1, g_h1);
    cudaGetSymbolAddress(&ps2, g_s2); cudaGetSymbolAddress(&ph2, g_h2);
    cudaGetSymbolAddress(&ps3, g_s3); cudaGetSymbolAddress(&ph3, g_h3);
    cudaGetSymbolAddress(&ps4, g_s4); cudaGetSymbolAddress(&ph4, g_h4);
    cudaGetSymbolAddress(&ps5, g_s5); cudaGetSymbolAddress(&ph5, g_h5);
    cudaGetSymbolAddress(&ps6, g_s6); cudaGetSymbolAddress(&ph6, g_h6);
    cudaGetSymbolAddress(&ps7, g_s7); cudaGetSymbolAddress(&ph7, g_h7);
    cudaGetSymbolAddress(&peb2, g_eb2); cudaGetSymbolAddress(&peb3, g_eb3);
    cudaGetSymbolAddress(&pebm2, g_ebm2); cudaGetSymbolAddress(&pebm3, g_ebm3);
    cudaGetSymbolAddress(&pZm1, g_Zm1); cudaGetSymbolAddress(&pZm2, g_Zm2);

    float* Z1 = (float*)pZ1;  float* Z2 = (float*)pZ2;  float* Z4 = (float*)pZ4;
    float* X  = (float*)pX;
    int* I1 = (int*)pI1;      int* I2 = (int*)pI2;

    // --- EdgeConv1 ---
    knn3_k<<<128, 256>>>(pos, I1);
    ec1_l0_k<<<NEDG * 4 / 256, 256>>>(pos, I1, c1w0, c1b0, Z1);
    stats_k<64><<<NBLK, 256>>>(Z1, NEDG / NBLK);
    finalize_k<<<8, 256>>>(64, (float)NEDG, NBLK, c1g0, c1e0, (float*)ps1, (float*)ph1);
    foldbias_k<<<1, 64>>>(64, 64, c1w1, c1b1, (float*)ph1, (float*)peb2);
    ec_mid_k<<<NEDG / 64, 256>>>(Z1, c1w1, (float*)ps1, (float*)peb2, Z2);
    stats_k<64><<<NBLK, 256>>>(Z2, NEDG / NBLK);
    finalize_k<<<8, 256>>>(64, (float)NEDG, NBLK, c1g1, c1e1, (float*)ps2, (float*)ph2);
    foldbias_k<<<1, 64>>>(64, 64, c1w2, c1b2, (float*)ph2, (float*)peb3);
    ec_mid_k<<<NEDG / 64, 256>>>(Z2, c1w2, (float*)ps2, (float*)peb3, Z1);
    stats_k<64><<<NBLK, 256>>>(Z1, NEDG / NBLK);
    finalize_k<<<8, 256>>>(64, (float)NEDG, NBLK, c1g2, c1e2, (float*)ps3, (float*)ph3);
    maxE_k<<<NPTS * 16 / 256, 256>>>(Z1, 64, (float*)ps3, (float*)ph3, X, 0, 1);

    // --- EdgeConv2 ---
    knn64_k<<<256, 256>>>((float*)pBD, (int*)pBI);
    knnmerge_k<<<NPTS / 256, 256>>>((float*)pBD, (int*)pBI, I2);
    ec2_k<<<NEDG / 64, 256>>>(X, I2, c2w, c2b, Z4);
    stats_k<128><<<NBLK, 256>>>(Z4, NEDG / NBLK);
    finalize_k<<<16, 256>>>(128, (float)NEDG, NBLK, c2g, c2e, (float*)ps4, (float*)ph4);
    maxE_k<<<NPTS * 32 / 256, 256>>>(Z4, 128, (float*)ps4, (float*)ph4, X, 64, 0);

    // --- fused l1 (GEMM + stats partials + max pool) ---
    initP1_k<<<64, 256>>>();
    l1_k<<<HRB * 8, 256>>>(X, l1w, l1b);
    finalize_k<<<128, 256>>>(1024, (float)NPTS, HRB, l1g, l1e, (float*)ps5, (float*)ph5);

    // --- head ---
    head1_k<<<32, 256>>>(m1w, m1b);
    stats16_k<<<2, 256>>>((float*)pZm1, 512, m1g, m1e, (float*)ps6, (float*)ph6);
    foldbias_k<<<1, 256>>>(512, 256, m2w, m2b, (float*)ph6, (float*)pebm2);
    head2_k<<<16, 256>>>(m2w);
    stats16_k<<<1, 256>>>((float*)pZm2, 256, m2g, m2e, (float*)ps7, (float*)ph7);
    foldbias_k<<<1, 32>>>(256, 2, m3w, m3b, (float*)ph7, (float*)pebm3);
    head3_k<<<1, 32>>>(m3w, (float*)d_out);
}